// round 3
// baseline (speedup 1.0000x reference)
#include <cuda_runtime.h>
#include <cuda_bf16.h>

// Problem constants
#define PW 32
#define PL 64
#define PK 512
#define PN 64
#define ROWS_PER_W (PL * PK)            // 32768
#define TOTAL_ROWS (PW * ROWS_PER_W)    // 1048576
#define EN_ELEMS   TOTAL_ROWS           // energies element count
#define MASK_ELEMS (PW * (PL - 1) * PK) // 1032192

// Scratch for the swap mask (no allocs allowed -> __device__ global)
__device__ unsigned char g_mask[MASK_ELEMS];

// ---------------------------------------------------------------------------
// Kernel 1: energies[w,l,k] = s^T Q_w s  via bf16-split MMA (fp32-exact)
//   Q_w = Qhi + Qmid + Qlo (3x bf16 => ~24 mantissa bits). s in {0,1} is exact
//   in bf16, so S@Q accumulated in fp32 matches an fp32 einsum to ~1e-6.
// CTA: 256 threads (8 warps). Warp tile: 16 rows x 64 cols. 4 row-tiles/CTA.
// ---------------------------------------------------------------------------

#define QT_STRIDE 72  // halves; word stride 36 -> (4g+tg) mod 32 distinct => conflict-free

__device__ __forceinline__ unsigned pack_bf16(float lo, float hi) {
    __nv_bfloat162 h = __floats2bfloat162_rn(lo, hi);  // x=lo (low 16 bits), y=hi
    return *reinterpret_cast<unsigned*>(&h);
}

__device__ __forceinline__ void mma_bf16(float* d, const unsigned* a, unsigned b0, unsigned b1) {
    asm volatile(
        "mma.sync.aligned.m16n8k16.row.col.f32.bf16.bf16.f32 "
        "{%0,%1,%2,%3}, {%4,%5,%6,%7}, {%8,%9}, {%0,%1,%2,%3};"
        : "+f"(d[0]), "+f"(d[1]), "+f"(d[2]), "+f"(d[3])
        : "r"(a[0]), "r"(a[1]), "r"(a[2]), "r"(a[3]), "r"(b0), "r"(b1));
}

__global__ void __launch_bounds__(256, 1)
energies_kernel(const float* __restrict__ states,
                const float* __restrict__ Qg,
                float* __restrict__ energies_out) {
    const int w        = blockIdx.y;       // 0..31
    const int cta_in_w = blockIdx.x;       // 0..63
    const int tid      = threadIdx.x;

    // Q^T splits in smem, layout QT[j][i] (halves), padded stride 72
    __shared__ __nv_bfloat16 sQT[3][PN * QT_STRIDE];

    const float* Qw = Qg + (size_t)w * PN * PN;
    for (int idx = tid; idx < PN * PN; idx += 256) {
        const int i = idx >> 6;
        const int j = idx & 63;
        float q = Qw[idx];
        __nv_bfloat16 h = __float2bfloat16(q);
        float r = q - __bfloat162float(h);
        __nv_bfloat16 m = __float2bfloat16(r);
        float r2 = r - __bfloat162float(m);
        __nv_bfloat16 lo = __float2bfloat16(r2);
        sQT[0][j * QT_STRIDE + i] = h;
        sQT[1][j * QT_STRIDE + i] = m;
        sQT[2][j * QT_STRIDE + i] = lo;
    }
    __syncthreads();

    const int warp = tid >> 5;
    const int lane = tid & 31;
    const int g  = lane >> 2;  // 0..7  (row within group)
    const int tg = lane & 3;   // 0..3  (thread-in-group)

    #pragma unroll 1
    for (int t = 0; t < 4; t++) {
        const int tile = cta_in_w * 4 + t;                      // 0..255 within w
        const int row_base = w * ROWS_PER_W + tile * 128 + warp * 16;

        const float* rowg  = states + (size_t)(row_base + g) * PN;
        const float* rowg8 = rowg + 8 * PN;

        // A fragments for all 4 k-chunks (kept for the epilogue dot too)
        unsigned af[4][4];
        #pragma unroll
        for (int kc = 0; kc < 4; kc++) {
            const int c0 = kc * 16 + tg * 2;
            float2 v;
            v = *reinterpret_cast<const float2*>(rowg  + c0);     af[kc][0] = pack_bf16(v.x, v.y);
            v = *reinterpret_cast<const float2*>(rowg8 + c0);     af[kc][1] = pack_bf16(v.x, v.y);
            v = *reinterpret_cast<const float2*>(rowg  + c0 + 8); af[kc][2] = pack_bf16(v.x, v.y);
            v = *reinterpret_cast<const float2*>(rowg8 + c0 + 8); af[kc][3] = pack_bf16(v.x, v.y);
        }

        float d[8][4];
        #pragma unroll
        for (int nt = 0; nt < 8; nt++)
            #pragma unroll
            for (int e = 0; e < 4; e++) d[nt][e] = 0.0f;

        #pragma unroll
        for (int sp = 0; sp < 3; sp++) {
            const __nv_bfloat16* qt = sQT[sp];
            #pragma unroll
            for (int kc = 0; kc < 4; kc++) {
                #pragma unroll
                for (int nt = 0; nt < 8; nt++) {
                    const int n = nt * 8 + g;
                    const unsigned b0 = *reinterpret_cast<const unsigned*>(qt + n * QT_STRIDE + kc * 16 + tg * 2);
                    const unsigned b1 = *reinterpret_cast<const unsigned*>(qt + n * QT_STRIDE + kc * 16 + tg * 2 + 8);
                    mma_bf16(d[nt], af[kc], b0, b1);
                }
            }
        }

        // Epilogue: E[r] = sum_j sQ[r][j] * s[r][j]. The s bits at exactly the
        // columns each lane's accumulators own are the retained A fragments:
        //   af[kc][0] <-> d[2kc]   rows g   (cols 16kc+2tg,+1)
        //   af[kc][1] <-> d[2kc]   rows g+8
        //   af[kc][2] <-> d[2kc+1] rows g
        //   af[kc][3] <-> d[2kc+1] rows g+8
        float eg = 0.0f, eg8 = 0.0f;
        #pragma unroll
        for (int kc = 0; kc < 4; kc++) {
            unsigned a;
            a = af[kc][0];
            if (a & 0xFFFFu) eg  += d[2 * kc][0];
            if (a >> 16)     eg  += d[2 * kc][1];
            a = af[kc][1];
            if (a & 0xFFFFu) eg8 += d[2 * kc][2];
            if (a >> 16)     eg8 += d[2 * kc][3];
            a = af[kc][2];
            if (a & 0xFFFFu) eg  += d[2 * kc + 1][0];
            if (a >> 16)     eg  += d[2 * kc + 1][1];
            a = af[kc][3];
            if (a & 0xFFFFu) eg8 += d[2 * kc + 1][2];
            if (a >> 16)     eg8 += d[2 * kc + 1][3];
        }
        eg  += __shfl_xor_sync(0xffffffffu, eg, 1);
        eg  += __shfl_xor_sync(0xffffffffu, eg, 2);
        eg8 += __shfl_xor_sync(0xffffffffu, eg8, 1);
        eg8 += __shfl_xor_sync(0xffffffffu, eg8, 2);
        if (tg == 0) {
            energies_out[row_base + g]     = eg;
            energies_out[row_base + 8 + g] = eg8;
        }
    }
}

// ---------------------------------------------------------------------------
// Kernel 2: mask[w,j,k] = u < exp((E[j+1]-E[j]) * (beta[j+1]-beta[j]))
// ---------------------------------------------------------------------------
__global__ void __launch_bounds__(256)
mask_kernel(const float* __restrict__ energies,
            const float* __restrict__ beta,
            const float* __restrict__ u) {
    const int idx = blockIdx.x * 256 + threadIdx.x;  // < MASK_ELEMS
    const int k = idx & 511;
    const int j = (idx >> 9) % 63;
    const int w = idx / (63 * 512);
    const float e1 = energies[(w * PL + j) * PK + k];
    const float e2 = energies[(w * PL + j + 1) * PK + k];
    const float db = beta[j + 1] - beta[j];
    const float delta = (e2 - e1) * db;
    g_mask[idx] = (u[idx] < expf(delta)) ? 1 : 0;
}

// ---------------------------------------------------------------------------
// Kernel 3: row-gather swap.
// Final semantics of the overlapping jax .at updates:
//   out[w,0]   = mask[w,0]   ? states[w,1]   : states[w,0]
//   out[w,l>0] = mask[w,l-1] ? states[w,l-1] : states[w,l]
// ---------------------------------------------------------------------------
__global__ void __launch_bounds__(256)
swap_kernel(const float* __restrict__ states,
            float* __restrict__ out_states) {
    const int tid = blockIdx.x * 256 + threadIdx.x;  // < TOTAL_ROWS * 16
    const int n4  = tid & 15;
    const int row = tid >> 4;
    const int k = row & 511;
    const int l = (row >> 9) & 63;
    const int w = row >> 15;

    const int j = (l == 0) ? 0 : (l - 1);
    const bool m = g_mask[(w * 63 + j) * PK + k] != 0;
    int src;
    if (l == 0) src = m ? 1 : 0;
    else        src = m ? (l - 1) : l;

    const size_t src_off = (((size_t)((w * PL + src) * PK + k)) << 6) + ((size_t)n4 << 2);
    const float4 v = *reinterpret_cast<const float4*>(states + src_off);
    *reinterpret_cast<float4*>(out_states + (((size_t)row) << 6) + ((size_t)n4 << 2)) = v;
}

// ---------------------------------------------------------------------------

extern "C" void kernel_launch(void* const* d_in, const int* in_sizes, int n_in,
                              void* d_out, int out_size) {
    const float* states = (const float*)d_in[0];  // (32,64,512,64) f32
    const float* Q      = (const float*)d_in[1];  // (32,64,64) f32
    const float* beta   = (const float*)d_in[2];  // (64,) f32
    const float* u      = (const float*)d_in[3];  // (32,63,512) f32

    float* energies   = (float*)d_out;            // first W*L*K elements
    float* out_states = (float*)d_out + EN_ELEMS; // then W*L*K*N elements

    dim3 egrid(64, PW);
    energies_kernel<<<egrid, 256>>>(states, Q, energies);

    mask_kernel<<<MASK_ELEMS / 256, 256>>>(energies, beta, u);

    swap_kernel<<<(TOTAL_ROWS * 16) / 256, 256>>>(states, out_states);
}